// round 3
// baseline (speedup 1.0000x reference)
#include <cuda_runtime.h>
#include <float.h>

// Problem constants (fixed by reference)
#define B_ 2
#define T_ 5
#define C_ 3
#define H_ 96
#define W_ 96
#define WS_ 9
#define WT_ 1
#define PS_ 5
#define PSD_ 7
#define K_ 10
#define S0_ 4
#define NH_ (H_ / S0_)
#define NW_ (W_ / S0_)
#define Q_ (T_ * NH_ * NW_)             // 2880
#define L_ ((2 * WT_ + 1) * WS_ * WS_)  // 243
#define LSELF_ (WT_ * WS_ * WS_ + (WS_ / 2) * WS_ + (WS_ / 2))  // 121
#define NDR_ ((K_ - 1) * C_ * PSD_ * PSD_)  // 1323
#define GRID_ (B_ * Q_)                 // 5760

// Tile: per (frame-slot, channel) plane of 15 rows, stride 17 (odd -> no
// systematic bank conflicts between candidate rows)
#define TR_ 15
#define TSTR_ 17
#define TPLANE_ (TR_ * TSTR_)           // 255

__device__ float g_part[GRID_];
__device__ unsigned int g_count;        // zero-initialized; reset by last block

__device__ __forceinline__ int refl(int i, int n) {
    i = i < 0 ? -i : i;
    return i >= n ? 2 * (n - 1) - i : i;
}
__device__ __forceinline__ int clampi(int i, int lo, int hi) {
    return min(max(i, lo), hi);
}

__global__ __launch_bounds__(256) void dnls_main_k(
    const float* __restrict__ noisy,
    const float* __restrict__ deno,
    float* __restrict__ out)
{
    const int blk = blockIdx.x;
    const int b = blk / Q_;
    const int q = blk % Q_;
    const int qt = q / (NH_ * NW_);
    const int qr = q % (NH_ * NW_);
    const int qh = (qr / NW_) * S0_;
    const int qw = (qr % NW_) * S0_;
    const int tid = threadIdx.x;

    __shared__ float tile[9 * TPLANE_];    // noisy: [slot*3+c][15][17]
    __shared__ float dtile[3 * TPLANE_];   // deno frame qt
    __shared__ float dsm[256];
    __shared__ int   sel[K_];
    __shared__ int   selt[K_ - 1], selh[K_ - 1], selw[K_ - 1];
    __shared__ float red[8];
    __shared__ int   is_last;

    const float* nb = noisy + (size_t)b * T_ * C_ * H_ * W_;
    const float* db = deno  + (size_t)b * T_ * C_ * H_ * W_;

    // All raw coords used anywhere lie in [qh-7,qh+7]x[qw-7,qw+7]; after
    // reflect/clamp they land in [rlo,rhi]x[clo,chi].
    const int rlo = max(0, qh - 7), rhi = min(H_ - 1, qh + 7);
    const int clo = max(0, qw - 7), chi = min(W_ - 1, qw + 7);
    const int Rn = rhi - rlo + 1, Cn = chi - clo + 1;

    // ---- Stage noisy region: 3 frame slots x 3 channels ----
    for (int idx = tid; idx < 9 * TPLANE_; idx += 256) {
        int plane = idx / TPLANE_;
        int rem   = idx % TPLANE_;
        int rr = rem / TSTR_, cc = rem % TSTR_;
        if (rr < Rn && cc < Cn) {
            int dti = plane / 3, c = plane % 3;
            int ft = clampi(qt + dti - WT_, 0, T_ - 1);
            tile[idx] = __ldg(&nb[(ft * C_ + c) * H_ * W_ + (rlo + rr) * W_ + (clo + cc)]);
        }
    }
    // ---- Stage deno region (frame qt) ----
    for (int idx = tid; idx < 3 * TPLANE_; idx += 256) {
        int c   = idx / TPLANE_;
        int rem = idx % TPLANE_;
        int rr = rem / TSTR_, cc = rem % TSTR_;
        if (rr < Rn && cc < Cn) {
            dtile[idx] = __ldg(&db[(qt * C_ + c) * H_ * W_ + (rlo + rr) * W_ + (clo + cc)]);
        }
    }
    if (tid >= L_) dsm[tid] = FLT_MAX;
    __syncthreads();

    // ---- Phase 1: 243 candidate distances, all reads from smem ----
    if (tid < L_) {
        int dti = tid / (WS_ * WS_);
        int rem = tid % (WS_ * WS_);
        int dhi = rem / WS_;
        int dwi = rem % WS_;
        int ch = clampi(qh + dhi - WS_ / 2, 0, H_ - 1);
        int cw = clampi(qw + dwi - WS_ / 2, 0, W_ - 1);

        int crow[PS_], ccol[PS_], qrow[PS_], qcol[PS_];
        #pragma unroll
        for (int d = 0; d < PS_; d++) {
            crow[d] = refl(ch + d - PS_ / 2, H_) - rlo;
            ccol[d] = refl(cw + d - PS_ / 2, W_) - clo;
            qrow[d] = refl(qh + d - PS_ / 2, H_) - rlo;
            qcol[d] = refl(qw + d - PS_ / 2, W_) - clo;
        }

        float acc0 = 0.0f, acc1 = 0.0f, acc2 = 0.0f;
        #pragma unroll
        for (int c = 0; c < C_; c++) {
            const float* tc = &tile[(dti * 3 + c) * TPLANE_];
            const float* tq = &tile[(1 * 3 + c) * TPLANE_];   // slot 1 = frame qt
            float a = 0.0f;
            #pragma unroll
            for (int dy = 0; dy < PS_; dy++) {
                const float* rq = tq + qrow[dy] * TSTR_;
                const float* rc = tc + crow[dy] * TSTR_;
                #pragma unroll
                for (int dx = 0; dx < PS_; dx++) {
                    float df = rq[qcol[dx]] - rc[ccol[dx]];
                    a = fmaf(df, df, a);
                }
            }
            if (c == 0) acc0 = a; else if (c == 1) acc1 = a; else acc2 = a;
        }
        float acc = (acc0 + acc1) + acc2;
        dsm[tid] = (tid == LSELF_) ? -1.0f : acc;
    }
    __syncthreads();

    // ---- Phase 2: K smallest, lowest-index tie-break (warp 0) ----
    if (tid < 32) {
        for (int k = 0; k < K_; k++) {
            float bd = FLT_MAX;
            int   bi = 1 << 20;
            for (int i = tid; i < L_; i += 32) {
                float v = dsm[i];
                if (v < bd) { bd = v; bi = i; }
            }
            #pragma unroll
            for (int off = 16; off; off >>= 1) {
                float od = __shfl_down_sync(0xffffffffu, bd, off);
                int   oi = __shfl_down_sync(0xffffffffu, bi, off);
                if (od < bd || (od == bd && oi < bi)) { bd = od; bi = oi; }
            }
            bi = __shfl_sync(0xffffffffu, bi, 0);
            if (tid == 0) { sel[k] = bi; dsm[bi] = FLT_MAX; }
            __syncwarp();
        }
    }
    __syncthreads();

    if (tid < K_ - 1) {
        int l = sel[tid + 1];
        int dti = l / (WS_ * WS_);
        int rem = l % (WS_ * WS_);
        selt[tid] = dti;
        selh[tid] = clampi(qh + rem / WS_ - WS_ / 2, 0, H_ - 1);
        selw[tid] = clampi(qw + rem % WS_ - WS_ / 2, 0, W_ - 1);
    }
    __syncthreads();

    // ---- Phase 3: dr over ranks 1..9, 3x7x7 patches, all from smem ----
    float part = 0.0f;
    for (int i = tid; i < NDR_; i += 256) {
        int k = i / (C_ * PSD_ * PSD_);
        int j = i % (C_ * PSD_ * PSD_);
        int c  = j / (PSD_ * PSD_);
        int rr = j % (PSD_ * PSD_);
        int dy = rr / PSD_ - PSD_ / 2;
        int dx = rr % PSD_ - PSD_ / 2;

        float pd = dtile[c * TPLANE_ +
                         (refl(qh + dy, H_) - rlo) * TSTR_ +
                         (refl(qw + dx, W_) - clo)];
        float pk = tile[(selt[k] * 3 + c) * TPLANE_ +
                        (refl(selh[k] + dy, H_) - rlo) * TSTR_ +
                        (refl(selw[k] + dx, W_) - clo)];
        float df = pd - pk;
        part = fmaf(df, df, part);
    }

    // ---- Block reduction -> per-CTA partial ----
    #pragma unroll
    for (int off = 16; off; off >>= 1)
        part += __shfl_down_sync(0xffffffffu, part, off);
    if ((tid & 31) == 0) red[tid >> 5] = part;
    __syncthreads();
    if (tid == 0) {
        float s = 0.0f;
        #pragma unroll
        for (int w = 0; w < 8; w++) s += red[w];
        g_part[blk] = s;
        __threadfence();
        unsigned int t = atomicAdd(&g_count, 1u);
        is_last = (t == GRID_ - 1) ? 1 : 0;
    }
    __syncthreads();

    // ---- Last CTA: final reduction over all partials ----
    if (is_last) {
        float s = 0.0f;
        const float4* p4 = (const float4*)g_part;    // GRID_ % 4 == 0
        for (int i = tid; i < GRID_ / 4; i += 256) {
            float4 v = p4[i];
            s += (v.x + v.y) + (v.z + v.w);
        }
        #pragma unroll
        for (int off = 16; off; off >>= 1)
            s += __shfl_down_sync(0xffffffffu, s, off);
        if ((tid & 31) == 0) red[tid >> 5] = s;
        __syncthreads();
        if (tid == 0) {
            float tsum = 0.0f;
            #pragma unroll
            for (int w = 0; w < 8; w++) tsum += red[w];
            out[0] = tsum * (1.0f / (float)(B_ * Q_ * (K_ - 1)));
            g_count = 0;   // reset for next graph replay (deterministic)
        }
    }
}

extern "C" void kernel_launch(void* const* d_in, const int* in_sizes, int n_in,
                              void* d_out, int out_size) {
    const float* noisy = (const float*)d_in[0];
    const float* deno  = (const float*)d_in[1];
    // d_in[2] = curr_epoch (unused by the reference computation)
    dnls_main_k<<<GRID_, 256>>>(noisy, deno, (float*)d_out);
}

// round 5
// speedup vs baseline: 1.3332x; 1.3332x over previous
#include <cuda_runtime.h>
#include <float.h>

#define B_ 2
#define T_ 5
#define C_ 3
#define H_ 96
#define W_ 96
#define WS_ 9
#define WT_ 1
#define PS_ 5
#define PSD_ 7
#define K_ 10
#define S0_ 4
#define NH_ (H_ / S0_)
#define NW_ (W_ / S0_)
#define Q_ (T_ * NH_ * NW_)             // 2880
#define L_ ((2 * WT_ + 1) * WS_ * WS_)  // 243
#define LSELF_ (WT_ * WS_ * WS_ + (WS_ / 2) * WS_ + (WS_ / 2))  // 121
#define GRID_ (B_ * Q_)                 // 5760
#define HW_ (H_ * W_)                   // 9216

#define TR_ 15
#define TSTR_ 17
#define TPLANE_ (TR_ * TSTR_)           // 255

__device__ float g_part[GRID_];

__device__ __forceinline__ int refl(int i, int n) {
    i = i < 0 ? -i : i;
    return i >= n ? 2 * (n - 1) - i : i;
}
__device__ __forceinline__ int clampi(int i, int lo, int hi) {
    return min(max(i, lo), hi);
}

__global__ __launch_bounds__(256) void dnls_main_k(
    const float* __restrict__ noisy,
    const float* __restrict__ deno)
{
    const int blk = blockIdx.x;
    const int b = blk / Q_;
    const int q = blk % Q_;
    const int qt = q / (NH_ * NW_);
    const int qr = q % (NH_ * NW_);
    const int qh = (qr / NW_) * S0_;
    const int qw = (qr % NW_) * S0_;
    const int tid = threadIdx.x;

    __shared__ float tile[9 * TPLANE_];    // noisy: [slot*3+c][15][17]
    __shared__ float dtile[3 * TPLANE_];   // deno frame qt
    __shared__ float dsm[256];
    __shared__ int   sel[K_];
    __shared__ int   kbarr[K_ - 1];        // fast path: per-k base offsets
    __shared__ int   selt[K_ - 1], selh[K_ - 1], selw[K_ - 1];
    __shared__ float red[8];

    const float* nb = noisy + (size_t)b * T_ * C_ * HW_;
    const float* db = deno  + (size_t)b * T_ * C_ * HW_;

    const int rlo = max(0, qh - 7), rhi = min(H_ - 1, qh + 7);
    const int clo = max(0, qw - 7), chi = min(W_ - 1, qw + 7);
    const int Rn = rhi - rlo + 1, Cn = chi - clo + 1;

    // Block-uniform: no reflect/clamp fires anywhere spatially
    const bool interior = (qh >= 8 && qh <= 88 && qw >= 8 && qw <= 88);

    if (tid >= L_) dsm[tid] = FLT_MAX;

    if (interior) {
        // ---- Fast staging: 15x15 region, no bounds checks, no div/mod ----
        if (tid < 240) {
            int rr = tid >> 4, cc = tid & 15;
            if (cc < 15) {
                int gb = (rlo + rr) * W_ + clo + cc;
                int sb = rr * TSTR_ + cc;
                #pragma unroll
                for (int p = 0; p < 9; p++) {
                    int dti = p / 3, c = p % 3;
                    int ft = clampi(qt + dti - WT_, 0, T_ - 1);
                    tile[p * TPLANE_ + sb] = __ldg(&nb[(ft * C_ + c) * HW_ + gb]);
                }
                #pragma unroll
                for (int c = 0; c < C_; c++)
                    dtile[c * TPLANE_ + sb] = __ldg(&db[(qt * C_ + c) * HW_ + gb]);
            }
        }
        __syncthreads();

        // ---- Phase 1 fast: all offsets immediate, 3 independent chains ----
        if (tid < L_) {
            int dti = tid / (WS_ * WS_);
            int rem = tid % (WS_ * WS_);
            int dhi = rem / WS_;
            int dwi = rem % WS_;
            const float* cb = &tile[dti * 3 * TPLANE_ + (dhi + 1) * TSTR_ + (dwi + 1)];
            const float* qb = &tile[1 * 3 * TPLANE_ + 5 * TSTR_ + 5];   // query patch
            float a0 = 0.0f, a1 = 0.0f, a2 = 0.0f;
            #pragma unroll
            for (int dy = 0; dy < PS_; dy++) {
                #pragma unroll
                for (int dx = 0; dx < PS_; dx++) {
                    float d0 = qb[0 * TPLANE_ + dy * TSTR_ + dx]
                             - cb[0 * TPLANE_ + dy * TSTR_ + dx];
                    a0 = fmaf(d0, d0, a0);
                    float d1 = qb[1 * TPLANE_ + dy * TSTR_ + dx]
                             - cb[1 * TPLANE_ + dy * TSTR_ + dx];
                    a1 = fmaf(d1, d1, a1);
                    float d2 = qb[2 * TPLANE_ + dy * TSTR_ + dx]
                             - cb[2 * TPLANE_ + dy * TSTR_ + dx];
                    a2 = fmaf(d2, d2, a2);
                }
            }
            float acc = (a0 + a1) + a2;
            dsm[tid] = (tid == LSELF_) ? -1.0f : acc;
        }
    } else {
        // ---- General staging (bounds-checked) ----
        for (int idx = tid; idx < 9 * TPLANE_; idx += 256) {
            int plane = idx / TPLANE_;
            int rem   = idx % TPLANE_;
            int rr = rem / TSTR_, cc = rem % TSTR_;
            if (rr < Rn && cc < Cn) {
                int dti = plane / 3, c = plane % 3;
                int ft = clampi(qt + dti - WT_, 0, T_ - 1);
                tile[idx] = __ldg(&nb[(ft * C_ + c) * HW_ + (rlo + rr) * W_ + (clo + cc)]);
            }
        }
        for (int idx = tid; idx < 3 * TPLANE_; idx += 256) {
            int c   = idx / TPLANE_;
            int rem = idx % TPLANE_;
            int rr = rem / TSTR_, cc = rem % TSTR_;
            if (rr < Rn && cc < Cn)
                dtile[idx] = __ldg(&db[(qt * C_ + c) * HW_ + (rlo + rr) * W_ + (clo + cc)]);
        }
        __syncthreads();

        // ---- Phase 1 general (reflect/clamp) ----
        if (tid < L_) {
            int dti = tid / (WS_ * WS_);
            int rem = tid % (WS_ * WS_);
            int dhi = rem / WS_;
            int dwi = rem % WS_;
            int ch = clampi(qh + dhi - WS_ / 2, 0, H_ - 1);
            int cw = clampi(qw + dwi - WS_ / 2, 0, W_ - 1);

            int crow[PS_], ccol[PS_], qrow[PS_], qcol[PS_];
            #pragma unroll
            for (int d = 0; d < PS_; d++) {
                crow[d] = refl(ch + d - PS_ / 2, H_) - rlo;
                ccol[d] = refl(cw + d - PS_ / 2, W_) - clo;
                qrow[d] = refl(qh + d - PS_ / 2, H_) - rlo;
                qcol[d] = refl(qw + d - PS_ / 2, W_) - clo;
            }
            float acc = 0.0f;
            #pragma unroll
            for (int c = 0; c < C_; c++) {
                const float* tc = &tile[(dti * 3 + c) * TPLANE_];
                const float* tq = &tile[(1 * 3 + c) * TPLANE_];
                #pragma unroll
                for (int dy = 0; dy < PS_; dy++) {
                    const float* rq = tq + qrow[dy] * TSTR_;
                    const float* rc = tc + crow[dy] * TSTR_;
                    #pragma unroll
                    for (int dx = 0; dx < PS_; dx++) {
                        float df = rq[qcol[dx]] - rc[ccol[dx]];
                        acc = fmaf(df, df, acc);
                    }
                }
            }
            dsm[tid] = (tid == LSELF_) ? -1.0f : acc;
        }
    }
    __syncthreads();

    // ---- Phase 2: K smallest, lowest-index tie-break (warp 0) ----
    if (tid < 32) {
        for (int k = 0; k < K_; k++) {
            float bd = FLT_MAX;
            int   bi = 1 << 20;
            for (int i = tid; i < L_; i += 32) {
                float v = dsm[i];
                if (v < bd) { bd = v; bi = i; }
            }
            #pragma unroll
            for (int off = 16; off; off >>= 1) {
                float od = __shfl_down_sync(0xffffffffu, bd, off);
                int   oi = __shfl_down_sync(0xffffffffu, bi, off);
                if (od < bd || (od == bd && oi < bi)) { bd = od; bi = oi; }
            }
            bi = __shfl_sync(0xffffffffu, bi, 0);
            if (tid == 0) { sel[k] = bi; dsm[bi] = FLT_MAX; }
            __syncwarp();
        }
    }
    __syncthreads();

    float part = 0.0f;
    if (interior) {
        // Precompute per-candidate base offsets (threads 0..8)
        if (tid < K_ - 1) {
            int l = sel[tid + 1];
            int dti = l / (WS_ * WS_);
            int rem = l % (WS_ * WS_);
            kbarr[tid] = dti * (3 * TPLANE_) + (rem / WS_) * TSTR_ + (rem % WS_);
        }
        __syncthreads();

        // ---- Phase 3 fast: thread = (c,dy0,dx0), pd loaded once, 9 unrolled k ----
        if (tid < C_ * PSD_ * PSD_) {       // 147 threads
            int c   = tid / (PSD_ * PSD_);
            int rr  = tid % (PSD_ * PSD_);
            int dy0 = rr / PSD_;
            int dx0 = rr % PSD_;
            int myoff = c * TPLANE_ + dy0 * TSTR_ + dx0;
            float pd = dtile[c * TPLANE_ + (dy0 + 4) * TSTR_ + (dx0 + 4)];
            int kb[K_ - 1];
            #pragma unroll
            for (int k = 0; k < K_ - 1; k++) kb[k] = kbarr[k];
            #pragma unroll
            for (int k = 0; k < K_ - 1; k++) {
                float df = pd - tile[kb[k] + myoff];
                part = fmaf(df, df, part);
            }
        }
    } else {
        if (tid < K_ - 1) {
            int l = sel[tid + 1];
            int dti = l / (WS_ * WS_);
            int rem = l % (WS_ * WS_);
            selt[tid] = dti;
            selh[tid] = clampi(qh + rem / WS_ - WS_ / 2, 0, H_ - 1);
            selw[tid] = clampi(qw + rem % WS_ - WS_ / 2, 0, W_ - 1);
        }
        __syncthreads();

        for (int i = tid; i < (K_ - 1) * C_ * PSD_ * PSD_; i += 256) {
            int k = i / (C_ * PSD_ * PSD_);
            int j = i % (C_ * PSD_ * PSD_);
            int c  = j / (PSD_ * PSD_);
            int rr = j % (PSD_ * PSD_);
            int dy = rr / PSD_ - PSD_ / 2;
            int dx = rr % PSD_ - PSD_ / 2;
            float pd = dtile[c * TPLANE_ +
                             (refl(qh + dy, H_) - rlo) * TSTR_ +
                             (refl(qw + dx, W_) - clo)];
            float pk = tile[(selt[k] * 3 + c) * TPLANE_ +
                            (refl(selh[k] + dy, H_) - rlo) * TSTR_ +
                            (refl(selw[k] + dx, W_) - clo)];
            float df = pd - pk;
            part = fmaf(df, df, part);
        }
    }

    // ---- Block reduction -> deterministic per-CTA partial ----
    #pragma unroll
    for (int off = 16; off; off >>= 1)
        part += __shfl_down_sync(0xffffffffu, part, off);
    if ((tid & 31) == 0) red[tid >> 5] = part;
    __syncthreads();
    if (tid == 0) {
        float s = 0.0f;
        #pragma unroll
        for (int w = 0; w < 8; w++) s += red[w];
        g_part[blk] = s;
    }
}

__global__ __launch_bounds__(256) void final_k(float* out) {
    __shared__ float red[8];
    const int tid = threadIdx.x;
    float s = 0.0f;
    const float4* p4 = (const float4*)g_part;     // GRID_ % 4 == 0
    for (int i = tid; i < GRID_ / 4; i += 256) {
        float4 v = p4[i];
        s += (v.x + v.y) + (v.z + v.w);
    }
    #pragma unroll
    for (int off = 16; off; off >>= 1)
        s += __shfl_down_sync(0xffffffffu, s, off);
    if ((tid & 31) == 0) red[tid >> 5] = s;
    __syncthreads();
    if (tid == 0) {
        float t = 0.0f;
        #pragma unroll
        for (int w = 0; w < 8; w++) t += red[w];
        out[0] = t * (1.0f / (float)(GRID_ * (K_ - 1)));
    }
}

extern "C" void kernel_launch(void* const* d_in, const int* in_sizes, int n_in,
                              void* d_out, int out_size) {
    const float* noisy = (const float*)d_in[0];
    const float* deno  = (const float*)d_in[1];
    // d_in[2] = curr_epoch (unused by the reference computation)
    dnls_main_k<<<GRID_, 256>>>(noisy, deno);
    final_k<<<1, 256>>>((float*)d_out);
}